// round 14
// baseline (speedup 1.0000x reference)
#include <cuda_runtime.h>
#include <cuda_bf16.h>
#include <cstdint>

// Problem constants
#define B     32
#define IN_CH 512
#define VD    16
#define HW    4096          // 64*64
#define NCLS  5
#define KSTEPS 64           // IN_CH / 8

typedef unsigned long long ULL;

// ---------------- device scratch (no allocs allowed) ----------------
__device__ float g_v[(size_t)B * HW * VD];   // 8 MB: root conv output, (b, slot, 16)
__device__ float g_part[512 * VD];           // per-block partial sums of v
__device__ float g_Asel[B * VD * VD];        // selected leaf composition matrix
__device__ float g_dvec[B * VD];             // selected leaf offset
__device__ float g_m2part[256];              // per-block partial sums of m2
__device__ int   g_ticket0;                  // k_root tail ticket
__device__ int   g_ticket1;                  // k_head finisher ticket

__device__ __forceinline__ ULL ffma2(ULL a, ULL b, ULL c) {
    ULL d;
    asm("fma.rn.f32x2 %0, %1, %2, %3;" : "=l"(d) : "l"(a), "l"(b), "l"(c));
    return d;
}
__device__ __forceinline__ ULL pack2(float lo, float hi) {
    float2 t = make_float2(lo, hi);
    return *reinterpret_cast<ULL*>(&t);
}
__device__ __forceinline__ float2 unpack2(ULL v) {
    return *reinterpret_cast<float2*>(&v);
}
__device__ __forceinline__ uint32_t f2tf32(float x) {
    uint32_t r;
    asm("cvt.rna.tf32.f32 %0, %1;" : "=r"(r) : "f"(x));
    return r;
}
__device__ __forceinline__ void mma_tf32(float* d, const uint32_t* a, uint32_t b0, uint32_t b1) {
    asm volatile(
        "mma.sync.aligned.m16n8k8.row.col.f32.tf32.tf32.f32 "
        "{%0,%1,%2,%3}, {%4,%5,%6,%7}, {%8,%9}, {%0,%1,%2,%3};"
        : "+f"(d[0]), "+f"(d[1]), "+f"(d[2]), "+f"(d[3])
        : "r"(a[0]), "r"(a[1]), "r"(a[2]), "r"(a[3]), "r"(b0), "r"(b1));
}

// ======================================================================
// Pass 1 (tensor-core, full-line loads): v = root_w @ features per pixel,
// plus a LAST-BLOCK TAIL that computes the whole tree recursion ONCE.
// ======================================================================
__global__ void __launch_bounds__(256, 4) k_root(const float* __restrict__ feat,
                                                 const float* __restrict__ root_w,
                                                 const float* __restrict__ root_b,
                                                 const float* __restrict__ level_w,
                                                 const float* __restrict__ level_b,
                                                 float* __restrict__ out) {
    __shared__ uint2 s_bl[KSTEPS * 32];   // 16KB: b-frags for out cols 0-7
    __shared__ uint2 s_bh[KSTEPS * 32];   // 16KB: b-frags for out cols 8-15
    __shared__ float sred[8][VD];

    const int b     = blockIdx.x >> 4;
    const int chunk = blockIdx.x & 15;
    const int tid   = threadIdx.x;
    const int warp  = tid >> 5, lane = tid & 31;
    const int gid   = lane >> 2, tg = lane & 3;

    for (int idx = tid; idx < KSTEPS * 32; idx += 256) {
        int s = idx >> 5, l = idx & 31;
        int g = l >> 2, t = l & 3;
        int k = 8 * s + t;
        s_bl[idx] = make_uint2(f2tf32(root_w[g * IN_CH + k]),
                               f2tf32(root_w[g * IN_CH + k + 4]));
        s_bh[idx] = make_uint2(f2tf32(root_w[(g + 8) * IN_CH + k]),
                               f2tf32(root_w[(g + 8) * IN_CH + k + 4]));
    }
    __syncthreads();

    const int pix0 = chunk * 256 + warp * 32;
    const float* lp = feat + (size_t)b * (IN_CH * HW) + (size_t)(lane >> 3) * HW
                    + pix0 + 4 * (lane & 7);
    const int src = (tg << 3) | gid;

    float d[2][2][4];
#pragma unroll
    for (int t = 0; t < 2; t++)
#pragma unroll
        for (int h = 0; h < 2; h++)
#pragma unroll
            for (int j = 0; j < 4; j++) d[t][h][j] = 0.f;

    float4 c1 = *reinterpret_cast<const float4*>(lp);
    float4 c2 = *reinterpret_cast<const float4*>(lp + (size_t)4 * HW);

#pragma unroll 4
    for (int s = 0; s < KSTEPS; s++) {
        const float* np = lp + (size_t)(((s + 1) & (KSTEPS - 1)) * 8) * HW;
        float4 n1 = *reinterpret_cast<const float4*>(np);
        float4 n2 = *reinterpret_cast<const float4*>(np + (size_t)4 * HW);

        uint32_t u1x = f2tf32(c1.x), u1y = f2tf32(c1.y), u1z = f2tf32(c1.z), u1w = f2tf32(c1.w);
        uint32_t u2x = f2tf32(c2.x), u2y = f2tf32(c2.y), u2z = f2tf32(c2.z), u2w = f2tf32(c2.w);

        uint32_t a0[4], a1[4];
        a0[0] = __shfl_sync(0xffffffffu, u1x, src);
        a0[1] = __shfl_sync(0xffffffffu, u1y, src);
        a1[0] = __shfl_sync(0xffffffffu, u1z, src);
        a1[1] = __shfl_sync(0xffffffffu, u1w, src);
        a0[2] = __shfl_sync(0xffffffffu, u2x, src);
        a0[3] = __shfl_sync(0xffffffffu, u2y, src);
        a1[2] = __shfl_sync(0xffffffffu, u2z, src);
        a1[3] = __shfl_sync(0xffffffffu, u2w, src);

        uint2 bl = s_bl[(s << 5) | lane];
        uint2 bh = s_bh[(s << 5) | lane];

        mma_tf32(d[0][0], a0, bl.x, bl.y);
        mma_tf32(d[0][1], a0, bh.x, bh.y);
        mma_tf32(d[1][0], a1, bl.x, bl.y);
        mma_tf32(d[1][1], a1, bh.x, bh.y);

        c1 = n1; c2 = n2;
    }

    // ---- store v (permuted pixel slots within the 32-px tile) ----
    float* vb = g_v + ((size_t)b * HW + pix0) * VD;
#pragma unroll
    for (int t = 0; t < 2; t++) {
#pragma unroll
        for (int h = 0; h < 2; h++) {
            *reinterpret_cast<float2*>(vb + (4 * gid + 2 * t) * VD + h * 8 + 2 * tg) =
                make_float2(d[t][h][0], d[t][h][1]);
            *reinterpret_cast<float2*>(vb + (4 * gid + 2 * t + 1) * VD + h * 8 + 2 * tg) =
                make_float2(d[t][h][2], d[t][h][3]);
        }
    }

    // ---- pooled sums over this warp's 32 pixels ----
    float s2[2][2];
#pragma unroll
    for (int h = 0; h < 2; h++) {
        s2[h][0] = d[0][h][0] + d[0][h][2] + d[1][h][0] + d[1][h][2];
        s2[h][1] = d[0][h][1] + d[0][h][3] + d[1][h][1] + d[1][h][3];
    }
#pragma unroll
    for (int off = 4; off < 32; off <<= 1) {
#pragma unroll
        for (int h = 0; h < 2; h++) {
            s2[h][0] += __shfl_xor_sync(0xffffffffu, s2[h][0], off);
            s2[h][1] += __shfl_xor_sync(0xffffffffu, s2[h][1], off);
        }
    }
    if (gid == 0) {
#pragma unroll
        for (int h = 0; h < 2; h++) {
            sred[warp][h * 8 + 2 * tg]     = s2[h][0];
            sred[warp][h * 8 + 2 * tg + 1] = s2[h][1];
        }
    }
    __syncthreads();
    if (tid < VD) {
        float t = 0.f;
#pragma unroll
        for (int w = 0; w < 8; w++) t += sred[w][tid];
        g_part[blockIdx.x * VD + tid] = t;
    }

    // ================= last-block tail: tree recursion, ONCE ============
    __shared__ int is_last;
    if (tid == 0) {
        __threadfence();
        is_last = (atomicAdd(&g_ticket0, 1) == (B * 16 - 1));
    }
    __syncthreads();
    if (!is_last) return;
    __threadfence();

    __shared__ float A[NCLS][VD][VD], Cv[NCLS][VD], Mu[NCLS][VD];
    __shared__ float An[NCLS][VD][VD], Cn[NCLS][VD], Mun[NCLS][VD];
    __shared__ float norms[NCLS];

    // loop over batches; all state is tiny, block-serial but only ~32*levels work
    for (int bb = 0; bb < B; bb++) {
        {
            int o = tid >> 4, i = tid & 15;
            A[0][o][i] = (o == i) ? 1.f : 0.f;
        }
        if (tid < VD) {
            float s = 0.f;
            for (int ch = 0; ch < 16; ch++) s += g_part[(bb * 16 + ch) * VD + tid];
            Mu[0][tid] = s * (1.0f / (float)HW) + root_b[tid];
            Cv[0][tid] = 0.f;
        }
        __syncthreads();

        for (int level = 1; level < NCLS; level++) {
            const int prevN = level, newN = level + 1;
            const int off = ((level - 1) * (level + 2)) >> 1;   // 0,2,5,9

            if (tid < prevN) {
                float s = 0.f;
                for (int k = 0; k < VD; k++) s += Mu[tid][k] * Mu[tid][k];
                norms[tid] = sqrtf(s);
            }
            __syncthreads();

            if (tid < newN * VD) {
                const int node = tid >> 4, o = tid & 15;
                int pl = node - 1; if (pl < 0) pl = 0;
                int pr = node;     if (pr > prevN - 1) pr = prevN - 1;
                const int ps = (pl == pr) ? pl : ((norms[pr] > norms[pl]) ? pr : pl);

                const float* W = level_w + (off + node) * (VD * VD) + o * VD;
                const float bv = level_b[(off + node) * VD + o];
                float cm = bv, mm = bv;
                float arow[VD];
#pragma unroll
                for (int i = 0; i < VD; i++) arow[i] = 0.f;
                for (int k = 0; k < VD; k++) {
                    const float w = W[k];
                    cm += w * Cv[ps][k];
                    mm += w * Mu[ps][k];
#pragma unroll
                    for (int i = 0; i < VD; i++) arow[i] += w * A[ps][k][i];
                }
                Cn[node][o] = cm;
                Mun[node][o] = mm;
#pragma unroll
                for (int i = 0; i < VD; i++) An[node][o][i] = arow[i];
            }
            __syncthreads();

            for (int idx = tid; idx < newN * VD * VD; idx += 256) {
                int node = idx >> 8, r = idx & 255;
                A[node][r >> 4][r & 15] = An[node][r >> 4][r & 15];
            }
            if (tid < newN * VD) {
                Cv[tid >> 4][tid & 15] = Cn[tid >> 4][tid & 15];
                Mu[tid >> 4][tid & 15] = Mun[tid >> 4][tid & 15];
            }
            __syncthreads();
        }

        if (tid < NCLS) {
            float s = 0.f;
            for (int k = 0; k < VD; k++) s += Mu[tid][k] * Mu[tid][k];
            norms[tid] = sqrtf(s);
            out[bb * NCLS + tid] = norms[tid];
        }
        __syncthreads();
        __shared__ int selsh;
        if (tid == 0) {
            int sel = 0; float best = norms[0];
            for (int n = 1; n < NCLS; n++) if (norms[n] > best) { best = norms[n]; sel = n; }
            selsh = sel;
            out[B * NCLS + B + bb] = (float)sel;
        }
        __syncthreads();
        const int sel = selsh;
        g_Asel[bb * 256 + tid] = A[sel][tid >> 4][tid & 15];
        if (tid < VD) {
            float s = Cv[sel][tid];
            for (int k = 0; k < VD; k++) s += A[sel][tid][k] * root_b[k];
            g_dvec[bb * VD + tid] = s;
        }
        __syncthreads();
    }
    if (tid == 0) g_ticket0 = 0;   // replay-safe reset
}

// ======================================================================
// Pass 2 (head + finisher): per-pixel f = A_sel@v + d, normalize, MLP,
// per-block partials; last block computes mantissa. grid 256.
// ======================================================================
__global__ void __launch_bounds__(256) k_head(const float* __restrict__ m1_w,
                                              const float* __restrict__ m1_b,
                                              const float* __restrict__ m2_w,
                                              const float* __restrict__ m2_b,
                                              float* __restrict__ out) {
    __shared__ ULL sAp[VD * VD];
    __shared__ ULL sdp[VD];
    __shared__ ULL sw1p[64 * VD];
    __shared__ ULL sb1p[64];
    __shared__ float sw2[64];
    __shared__ float sb2;
    const int b = blockIdx.x >> 3, chunk = blockIdx.x & 7;
    const int tid = threadIdx.x;

    {
        float a = g_Asel[b * 256 + tid];
        sAp[tid] = pack2(a, a);
    }
    for (int i = tid; i < 64 * VD; i += 256) {
        float w = m1_w[i];
        sw1p[i] = pack2(w, w);
    }
    if (tid < 64) {
        float bb = m1_b[tid];
        sb1p[tid] = pack2(bb, bb);
        sw2[tid] = m2_w[tid];
    }
    if (tid < VD) {
        float dv = g_dvec[b * VD + tid];
        sdp[tid] = pack2(dv, dv);
    }
    if (tid == 0) sb2 = m2_b[0];
    __syncthreads();

    const int pix0 = chunk * 512 + tid * 2;
    const float4* vp = reinterpret_cast<const float4*>(g_v + ((size_t)b * HW + pix0) * VD);

    float va0[VD], va1[VD];
#pragma unroll
    for (int q = 0; q < 4; q++) {
        float4 t0 = vp[q], t1 = vp[4 + q];
        va0[4*q+0] = t0.x; va0[4*q+1] = t0.y; va0[4*q+2] = t0.z; va0[4*q+3] = t0.w;
        va1[4*q+0] = t1.x; va1[4*q+1] = t1.y; va1[4*q+2] = t1.z; va1[4*q+3] = t1.w;
    }
    ULL v2[VD];
#pragma unroll
    for (int k = 0; k < VD; k++) v2[k] = pack2(va0[k], va1[k]);

    ULL f2[VD];
#pragma unroll
    for (int o = 0; o < VD; o++) {
        ULL t = sdp[o];
#pragma unroll
        for (int k = 0; k < VD; k++) t = ffma2(sAp[o * VD + k], v2[k], t);
        f2[o] = t;
    }

    float n20 = 0.f, n21 = 0.f;
#pragma unroll
    for (int o = 0; o < VD; o++) {
        float2 t = unpack2(f2[o]);
        n20 += t.x * t.x; n21 += t.y * t.y;
    }
    const ULL inv2 = pack2(1.0f / (sqrtf(n20) + 1e-8f),
                           1.0f / (sqrtf(n21) + 1e-8f));

    float m2a0 = 0.f, m2a1 = 0.f;
#pragma unroll 8
    for (int j = 0; j < 64; j++) {
        ULL t2 = pack2(0.f, 0.f);
#pragma unroll
        for (int o = 0; o < VD; o++) t2 = ffma2(sw1p[j * VD + o], f2[o], t2);
        t2 = ffma2(t2, inv2, sb1p[j]);
        float2 t = unpack2(t2);
        m2a0 += sw2[j] * fmaxf(t.x, 0.f);
        m2a1 += sw2[j] * fmaxf(t.y, 0.f);
    }
    float ssum = (m2a0 + m2a1) + 2.0f * sb2;

    __shared__ float red[8];
    __shared__ int is_last;
    const int lane = tid & 31, wid = tid >> 5;
#pragma unroll
    for (int off = 16; off; off >>= 1) ssum += __shfl_xor_sync(0xffffffffu, ssum, off);
    if (lane == 0) red[wid] = ssum;
    __syncthreads();
    if (tid == 0) {
        float t = 0.f;
#pragma unroll
        for (int w = 0; w < 8; w++) t += red[w];
        g_m2part[blockIdx.x] = t;
        __threadfence();
        is_last = (atomicAdd(&g_ticket1, 1) == 255);
    }
    __syncthreads();

    if (is_last) {
        __threadfence();
        if (tid < B) {
            float s = 0.f;
#pragma unroll
            for (int c = 0; c < 8; c++) s += g_m2part[tid * 8 + c];
            const float x = s * (1.0f / (float)HW);
            out[B * NCLS + tid] = 0.75f / (1.0f + expf(-x)) + 0.75f;
        }
        if (tid == 0) g_ticket1 = 0;   // replay-safe reset
    }
}

// ======================================================================
extern "C" void kernel_launch(void* const* d_in, const int* in_sizes, int n_in,
                              void* d_out, int out_size) {
    const float* features = (const float*)d_in[0];
    const float* root_w   = (const float*)d_in[1];
    const float* root_b   = (const float*)d_in[2];
    const float* level_w  = (const float*)d_in[3];
    const float* level_b  = (const float*)d_in[4];
    const float* m1_w     = (const float*)d_in[5];
    const float* m1_b     = (const float*)d_in[6];
    const float* m2_w     = (const float*)d_in[7];
    const float* m2_b     = (const float*)d_in[8];
    float* out = (float*)d_out;

    k_root<<<B * 16, 256>>>(features, root_w, root_b, level_w, level_b, out);
    k_head<<<B * 8, 256>>>(m1_w, m1_b, m2_w, m2_b, out);
}

// round 15
// speedup vs baseline: 3.9516x; 3.9516x over previous
#include <cuda_runtime.h>
#include <cuda_bf16.h>
#include <cstdint>

// Problem constants
#define B     32
#define IN_CH 512
#define VD    16
#define HW    4096          // 64*64
#define NCLS  5
#define KSTEPS 64           // IN_CH / 8

typedef unsigned long long ULL;

// ---------------- device scratch (no allocs allowed) ----------------
__device__ float g_v[(size_t)B * HW * VD];   // 8 MB: root conv output, (b, slot, 16)
__device__ float g_part[512 * VD];           // per-block partial sums of v
__device__ float g_Asel[B * VD * VD];        // selected leaf composition matrix
__device__ float g_dvec[B * VD];             // selected leaf offset
__device__ float g_m2part[256];              // per-block partial sums of m2
__device__ int   g_ticket1;                  // k_head finisher ticket

__device__ __forceinline__ ULL ffma2(ULL a, ULL b, ULL c) {
    ULL d;
    asm("fma.rn.f32x2 %0, %1, %2, %3;" : "=l"(d) : "l"(a), "l"(b), "l"(c));
    return d;
}
__device__ __forceinline__ ULL pack2(float lo, float hi) {
    float2 t = make_float2(lo, hi);
    return *reinterpret_cast<ULL*>(&t);
}
__device__ __forceinline__ float2 unpack2(ULL v) {
    return *reinterpret_cast<float2*>(&v);
}
__device__ __forceinline__ uint32_t f2tf32(float x) {
    uint32_t r;
    asm("cvt.rna.tf32.f32 %0, %1;" : "=r"(r) : "f"(x));
    return r;
}
__device__ __forceinline__ void mma_tf32(float* d, const uint32_t* a, uint32_t b0, uint32_t b1) {
    asm volatile(
        "mma.sync.aligned.m16n8k8.row.col.f32.tf32.tf32.f32 "
        "{%0,%1,%2,%3}, {%4,%5,%6,%7}, {%8,%9}, {%0,%1,%2,%3};"
        : "+f"(d[0]), "+f"(d[1]), "+f"(d[2]), "+f"(d[3])
        : "r"(a[0]), "r"(a[1]), "r"(a[2]), "r"(a[3]), "r"(b0), "r"(b1));
}

// ======================================================================
// Pass 1 (tensor-core, full-line loads): v = root_w @ features per pixel.
// EXACT R13 mainloop — no tail, no extra smem, regs stay ~56.
// ======================================================================
__global__ void __launch_bounds__(256, 4) k_root(const float* __restrict__ feat,
                                                 const float* __restrict__ root_w) {
    __shared__ uint2 s_bl[KSTEPS * 32];   // 16KB: b-frags for out cols 0-7
    __shared__ uint2 s_bh[KSTEPS * 32];   // 16KB: b-frags for out cols 8-15
    __shared__ float sred[8][VD];

    const int b     = blockIdx.x >> 4;
    const int chunk = blockIdx.x & 15;
    const int tid   = threadIdx.x;
    const int warp  = tid >> 5, lane = tid & 31;
    const int gid   = lane >> 2, tg = lane & 3;

    for (int idx = tid; idx < KSTEPS * 32; idx += 256) {
        int s = idx >> 5, l = idx & 31;
        int g = l >> 2, t = l & 3;
        int k = 8 * s + t;
        s_bl[idx] = make_uint2(f2tf32(root_w[g * IN_CH + k]),
                               f2tf32(root_w[g * IN_CH + k + 4]));
        s_bh[idx] = make_uint2(f2tf32(root_w[(g + 8) * IN_CH + k]),
                               f2tf32(root_w[(g + 8) * IN_CH + k + 4]));
    }
    __syncthreads();

    const int pix0 = chunk * 256 + warp * 32;
    const float* lp = feat + (size_t)b * (IN_CH * HW) + (size_t)(lane >> 3) * HW
                    + pix0 + 4 * (lane & 7);
    const int src = (tg << 3) | gid;

    float d[2][2][4];
#pragma unroll
    for (int t = 0; t < 2; t++)
#pragma unroll
        for (int h = 0; h < 2; h++)
#pragma unroll
            for (int j = 0; j < 4; j++) d[t][h][j] = 0.f;

    float4 c1 = *reinterpret_cast<const float4*>(lp);
    float4 c2 = *reinterpret_cast<const float4*>(lp + (size_t)4 * HW);

#pragma unroll 4
    for (int s = 0; s < KSTEPS; s++) {
        const float* np = lp + (size_t)(((s + 1) & (KSTEPS - 1)) * 8) * HW;
        float4 n1 = *reinterpret_cast<const float4*>(np);
        float4 n2 = *reinterpret_cast<const float4*>(np + (size_t)4 * HW);

        uint32_t u1x = f2tf32(c1.x), u1y = f2tf32(c1.y), u1z = f2tf32(c1.z), u1w = f2tf32(c1.w);
        uint32_t u2x = f2tf32(c2.x), u2y = f2tf32(c2.y), u2z = f2tf32(c2.z), u2w = f2tf32(c2.w);

        uint32_t a0[4], a1[4];
        a0[0] = __shfl_sync(0xffffffffu, u1x, src);
        a0[1] = __shfl_sync(0xffffffffu, u1y, src);
        a1[0] = __shfl_sync(0xffffffffu, u1z, src);
        a1[1] = __shfl_sync(0xffffffffu, u1w, src);
        a0[2] = __shfl_sync(0xffffffffu, u2x, src);
        a0[3] = __shfl_sync(0xffffffffu, u2y, src);
        a1[2] = __shfl_sync(0xffffffffu, u2z, src);
        a1[3] = __shfl_sync(0xffffffffu, u2w, src);

        uint2 bl = s_bl[(s << 5) | lane];
        uint2 bh = s_bh[(s << 5) | lane];

        mma_tf32(d[0][0], a0, bl.x, bl.y);
        mma_tf32(d[0][1], a0, bh.x, bh.y);
        mma_tf32(d[1][0], a1, bl.x, bl.y);
        mma_tf32(d[1][1], a1, bh.x, bh.y);

        c1 = n1; c2 = n2;
    }

    // ---- store v (permuted pixel slots within the 32-px tile) ----
    float* vb = g_v + ((size_t)b * HW + pix0) * VD;
#pragma unroll
    for (int t = 0; t < 2; t++) {
#pragma unroll
        for (int h = 0; h < 2; h++) {
            *reinterpret_cast<float2*>(vb + (4 * gid + 2 * t) * VD + h * 8 + 2 * tg) =
                make_float2(d[t][h][0], d[t][h][1]);
            *reinterpret_cast<float2*>(vb + (4 * gid + 2 * t + 1) * VD + h * 8 + 2 * tg) =
                make_float2(d[t][h][2], d[t][h][3]);
        }
    }

    // ---- pooled sums over this warp's 32 pixels ----
    float s2[2][2];
#pragma unroll
    for (int h = 0; h < 2; h++) {
        s2[h][0] = d[0][h][0] + d[0][h][2] + d[1][h][0] + d[1][h][2];
        s2[h][1] = d[0][h][1] + d[0][h][3] + d[1][h][1] + d[1][h][3];
    }
#pragma unroll
    for (int off = 4; off < 32; off <<= 1) {
#pragma unroll
        for (int h = 0; h < 2; h++) {
            s2[h][0] += __shfl_xor_sync(0xffffffffu, s2[h][0], off);
            s2[h][1] += __shfl_xor_sync(0xffffffffu, s2[h][1], off);
        }
    }
    if (gid == 0) {
#pragma unroll
        for (int h = 0; h < 2; h++) {
            sred[warp][h * 8 + 2 * tg]     = s2[h][0];
            sred[warp][h * 8 + 2 * tg + 1] = s2[h][1];
        }
    }
    __syncthreads();
    if (tid < VD) {
        float t = 0.f;
#pragma unroll
        for (int w = 0; w < 8; w++) t += sred[w][tid];
        g_part[blockIdx.x * VD + tid] = t;
    }
}

// ======================================================================
// Pass 2: tree recursion, ONE block per batch (grid 32). Tiny.
// ======================================================================
__global__ void __launch_bounds__(256) k_tree(const float* __restrict__ root_b,
                                              const float* __restrict__ level_w,
                                              const float* __restrict__ level_b,
                                              float* __restrict__ out) {
    const int b = blockIdx.x;
    const int tid = threadIdx.x;

    __shared__ float A[NCLS][VD][VD], Cv[NCLS][VD], Mu[NCLS][VD];
    __shared__ float An[NCLS][VD][VD], Cn[NCLS][VD], Mun[NCLS][VD];
    __shared__ float norms[NCLS];
    __shared__ int selsh;

    {
        int o = tid >> 4, i = tid & 15;
        A[0][o][i] = (o == i) ? 1.f : 0.f;
    }
    if (tid < VD) {
        float s = 0.f;
        for (int ch = 0; ch < 16; ch++) s += g_part[(b * 16 + ch) * VD + tid];
        Mu[0][tid] = s * (1.0f / (float)HW) + root_b[tid];
        Cv[0][tid] = 0.f;
    }
    __syncthreads();

    for (int level = 1; level < NCLS; level++) {
        const int prevN = level, newN = level + 1;
        const int off = ((level - 1) * (level + 2)) >> 1;   // 0,2,5,9

        if (tid < prevN) {
            float s = 0.f;
            for (int k = 0; k < VD; k++) s += Mu[tid][k] * Mu[tid][k];
            norms[tid] = sqrtf(s);
        }
        __syncthreads();

        if (tid < newN * VD) {
            const int node = tid >> 4, o = tid & 15;
            int pl = node - 1; if (pl < 0) pl = 0;
            int pr = node;     if (pr > prevN - 1) pr = prevN - 1;
            const int ps = (pl == pr) ? pl : ((norms[pr] > norms[pl]) ? pr : pl);

            const float* W = level_w + (off + node) * (VD * VD) + o * VD;
            const float bb = level_b[(off + node) * VD + o];
            float cm = bb, mm = bb;
            float arow[VD];
#pragma unroll
            for (int i = 0; i < VD; i++) arow[i] = 0.f;
            for (int k = 0; k < VD; k++) {
                const float w = W[k];
                cm += w * Cv[ps][k];
                mm += w * Mu[ps][k];
#pragma unroll
                for (int i = 0; i < VD; i++) arow[i] += w * A[ps][k][i];
            }
            Cn[node][o] = cm;
            Mun[node][o] = mm;
#pragma unroll
            for (int i = 0; i < VD; i++) An[node][o][i] = arow[i];
        }
        __syncthreads();

        for (int idx = tid; idx < newN * VD * VD; idx += 256) {
            int node = idx >> 8, r = idx & 255;
            A[node][r >> 4][r & 15] = An[node][r >> 4][r & 15];
        }
        if (tid < newN * VD) {
            Cv[tid >> 4][tid & 15] = Cn[tid >> 4][tid & 15];
            Mu[tid >> 4][tid & 15] = Mun[tid >> 4][tid & 15];
        }
        __syncthreads();
    }

    if (tid < NCLS) {
        float s = 0.f;
        for (int k = 0; k < VD; k++) s += Mu[tid][k] * Mu[tid][k];
        norms[tid] = sqrtf(s);
        out[b * NCLS + tid] = norms[tid];
    }
    __syncthreads();
    if (tid == 0) {
        int sel = 0; float best = norms[0];
        for (int n = 1; n < NCLS; n++) if (norms[n] > best) { best = norms[n]; sel = n; }
        selsh = sel;
        out[B * NCLS + B + b] = (float)sel;
    }
    __syncthreads();
    const int sel = selsh;
    g_Asel[b * 256 + tid] = A[sel][tid >> 4][tid & 15];
    if (tid < VD) {
        float s = Cv[sel][tid];
        for (int k = 0; k < VD; k++) s += A[sel][tid][k] * root_b[k];
        g_dvec[b * VD + tid] = s;
    }
}

// ======================================================================
// Pass 3 (head + finisher): per-pixel f = A_sel@v + d, normalize, MLP,
// per-block partials; last block computes mantissa. grid 256.
// MLP weight reads vectorized as LDS.128 (ulonglong2) to halve MIO traffic.
// ======================================================================
__global__ void __launch_bounds__(256) k_head(const float* __restrict__ m1_w,
                                              const float* __restrict__ m1_b,
                                              const float* __restrict__ m2_w,
                                              const float* __restrict__ m2_b,
                                              float* __restrict__ out) {
    __shared__ ULL sAp[VD * VD];
    __shared__ ULL sdp[VD];
    __shared__ ULL sw1p[64 * VD];     // 16B-aligned, read as ulonglong2
    __shared__ ULL sb1p[64];
    __shared__ float sw2[64];
    __shared__ float sb2;
    const int b = blockIdx.x >> 3, chunk = blockIdx.x & 7;
    const int tid = threadIdx.x;

    {
        float a = g_Asel[b * 256 + tid];
        sAp[tid] = pack2(a, a);
    }
    for (int i = tid; i < 64 * VD; i += 256) {
        float w = m1_w[i];
        sw1p[i] = pack2(w, w);
    }
    if (tid < 64) {
        float bb = m1_b[tid];
        sb1p[tid] = pack2(bb, bb);
        sw2[tid] = m2_w[tid];
    }
    if (tid < VD) {
        float dv = g_dvec[b * VD + tid];
        sdp[tid] = pack2(dv, dv);
    }
    if (tid == 0) sb2 = m2_b[0];
    __syncthreads();

    const int pix0 = chunk * 512 + tid * 2;
    const float4* vp = reinterpret_cast<const float4*>(g_v + ((size_t)b * HW + pix0) * VD);

    float va0[VD], va1[VD];
#pragma unroll
    for (int q = 0; q < 4; q++) {
        float4 t0 = vp[q], t1 = vp[4 + q];
        va0[4*q+0] = t0.x; va0[4*q+1] = t0.y; va0[4*q+2] = t0.z; va0[4*q+3] = t0.w;
        va1[4*q+0] = t1.x; va1[4*q+1] = t1.y; va1[4*q+2] = t1.z; va1[4*q+3] = t1.w;
    }
    ULL v2[VD];
#pragma unroll
    for (int k = 0; k < VD; k++) v2[k] = pack2(va0[k], va1[k]);

    // f = A@v + d  (packed, LDS.128 weight reads)
    ULL f2[VD];
#pragma unroll
    for (int o = 0; o < VD; o++) {
        ULL t = sdp[o];
        const ulonglong2* av = reinterpret_cast<const ulonglong2*>(sAp + o * VD);
#pragma unroll
        for (int q = 0; q < 8; q++) {
            ulonglong2 ap = av[q];
            t = ffma2(ap.x, v2[2 * q],     t);
            t = ffma2(ap.y, v2[2 * q + 1], t);
        }
        f2[o] = t;
    }

    float n20 = 0.f, n21 = 0.f;
#pragma unroll
    for (int o = 0; o < VD; o++) {
        float2 t = unpack2(f2[o]);
        n20 += t.x * t.x; n21 += t.y * t.y;
    }
    const ULL inv2 = pack2(1.0f / (sqrtf(n20) + 1e-8f),
                           1.0f / (sqrtf(n21) + 1e-8f));

    float m2a0 = 0.f, m2a1 = 0.f;
#pragma unroll 4
    for (int j = 0; j < 64; j++) {
        ULL t2 = pack2(0.f, 0.f);
        const ulonglong2* wv = reinterpret_cast<const ulonglong2*>(sw1p + j * VD);
#pragma unroll
        for (int q = 0; q < 8; q++) {
            ulonglong2 wp = wv[q];
            t2 = ffma2(wp.x, f2[2 * q],     t2);
            t2 = ffma2(wp.y, f2[2 * q + 1], t2);
        }
        t2 = ffma2(t2, inv2, sb1p[j]);
        float2 t = unpack2(t2);
        m2a0 += sw2[j] * fmaxf(t.x, 0.f);
        m2a1 += sw2[j] * fmaxf(t.y, 0.f);
    }
    float ssum = (m2a0 + m2a1) + 2.0f * sb2;

    __shared__ float red[8];
    __shared__ int is_last;
    const int lane = tid & 31, wid = tid >> 5;
#pragma unroll
    for (int off = 16; off; off >>= 1) ssum += __shfl_xor_sync(0xffffffffu, ssum, off);
    if (lane == 0) red[wid] = ssum;
    __syncthreads();
    if (tid == 0) {
        float t = 0.f;
#pragma unroll
        for (int w = 0; w < 8; w++) t += red[w];
        g_m2part[blockIdx.x] = t;
        __threadfence();
        is_last = (atomicAdd(&g_ticket1, 1) == 255);
    }
    __syncthreads();

    if (is_last) {
        __threadfence();
        if (tid < B) {
            float s = 0.f;
#pragma unroll
            for (int c = 0; c < 8; c++) s += g_m2part[tid * 8 + c];
            const float x = s * (1.0f / (float)HW);
            out[B * NCLS + tid] = 0.75f / (1.0f + expf(-x)) + 0.75f;
        }
        if (tid == 0) g_ticket1 = 0;   // replay-safe reset
    }
}

// ======================================================================
extern "C" void kernel_launch(void* const* d_in, const int* in_sizes, int n_in,
                              void* d_out, int out_size) {
    const float* features = (const float*)d_in[0];
    const float* root_w   = (const float*)d_in[1];
    const float* root_b   = (const float*)d_in[2];
    const float* level_w  = (const float*)d_in[3];
    const float* level_b  = (const float*)d_in[4];
    const float* m1_w     = (const float*)d_in[5];
    const float* m1_b     = (const float*)d_in[6];
    const float* m2_w     = (const float*)d_in[7];
    const float* m2_b     = (const float*)d_in[8];
    float* out = (float*)d_out;

    k_root<<<B * 16, 256>>>(features, root_w);
    k_tree<<<B, 256>>>(root_b, level_w, level_b, out);
    k_head<<<B * 8, 256>>>(m1_w, m1_b, m2_w, m2_b, out);
}

// round 16
// speedup vs baseline: 4.2483x; 1.0751x over previous
#include <cuda_runtime.h>
#include <cuda_bf16.h>
#include <cstdint>

// Problem constants
#define B     32
#define IN_CH 512
#define VD    16
#define HW    4096          // 64*64
#define NCLS  5
#define KSTEPS 64           // IN_CH / 8

typedef unsigned long long ULL;

// ---------------- device scratch (no allocs allowed) ----------------
__device__ float g_v[(size_t)B * HW * VD];   // 8 MB: root conv output, (b, slot, 16)
__device__ float g_part[512 * VD];           // per-block partial sums of v
__device__ float g_Asel[B * VD * VD];        // selected leaf composition matrix
__device__ float g_dvec[B * VD];             // selected leaf offset
__device__ float g_m2part[256];              // per-block partial sums of m2
__device__ int   g_ticket1;                  // k_head finisher ticket

__device__ __forceinline__ uint32_t f2tf32(float x) {
    uint32_t r;
    asm("cvt.rna.tf32.f32 %0, %1;" : "=r"(r) : "f"(x));
    return r;
}
__device__ __forceinline__ void mma_tf32(float* d, const uint32_t* a, uint32_t b0, uint32_t b1) {
    asm volatile(
        "mma.sync.aligned.m16n8k8.row.col.f32.tf32.tf32.f32 "
        "{%0,%1,%2,%3}, {%4,%5,%6,%7}, {%8,%9}, {%0,%1,%2,%3};"
        : "+f"(d[0]), "+f"(d[1]), "+f"(d[2]), "+f"(d[3])
        : "r"(a[0]), "r"(a[1]), "r"(a[2]), "r"(a[3]), "r"(b0), "r"(b1));
}

// ======================================================================
// Pass 1 (tensor-core, full-line loads): v = root_w @ features per pixel.
// EXACT R15 mainloop (50.3us, 69% DRAM).
// ======================================================================
__global__ void __launch_bounds__(256, 4) k_root(const float* __restrict__ feat,
                                                 const float* __restrict__ root_w) {
    __shared__ uint2 s_bl[KSTEPS * 32];
    __shared__ uint2 s_bh[KSTEPS * 32];
    __shared__ float sred[8][VD];

    const int b     = blockIdx.x >> 4;
    const int chunk = blockIdx.x & 15;
    const int tid   = threadIdx.x;
    const int warp  = tid >> 5, lane = tid & 31;
    const int gid   = lane >> 2, tg = lane & 3;

    for (int idx = tid; idx < KSTEPS * 32; idx += 256) {
        int s = idx >> 5, l = idx & 31;
        int g = l >> 2, t = l & 3;
        int k = 8 * s + t;
        s_bl[idx] = make_uint2(f2tf32(root_w[g * IN_CH + k]),
                               f2tf32(root_w[g * IN_CH + k + 4]));
        s_bh[idx] = make_uint2(f2tf32(root_w[(g + 8) * IN_CH + k]),
                               f2tf32(root_w[(g + 8) * IN_CH + k + 4]));
    }
    __syncthreads();

    const int pix0 = chunk * 256 + warp * 32;
    const float* lp = feat + (size_t)b * (IN_CH * HW) + (size_t)(lane >> 3) * HW
                    + pix0 + 4 * (lane & 7);
    const int src = (tg << 3) | gid;

    float d[2][2][4];
#pragma unroll
    for (int t = 0; t < 2; t++)
#pragma unroll
        for (int h = 0; h < 2; h++)
#pragma unroll
            for (int j = 0; j < 4; j++) d[t][h][j] = 0.f;

    float4 c1 = *reinterpret_cast<const float4*>(lp);
    float4 c2 = *reinterpret_cast<const float4*>(lp + (size_t)4 * HW);

#pragma unroll 4
    for (int s = 0; s < KSTEPS; s++) {
        const float* np = lp + (size_t)(((s + 1) & (KSTEPS - 1)) * 8) * HW;
        float4 n1 = *reinterpret_cast<const float4*>(np);
        float4 n2 = *reinterpret_cast<const float4*>(np + (size_t)4 * HW);

        uint32_t u1x = f2tf32(c1.x), u1y = f2tf32(c1.y), u1z = f2tf32(c1.z), u1w = f2tf32(c1.w);
        uint32_t u2x = f2tf32(c2.x), u2y = f2tf32(c2.y), u2z = f2tf32(c2.z), u2w = f2tf32(c2.w);

        uint32_t a0[4], a1[4];
        a0[0] = __shfl_sync(0xffffffffu, u1x, src);
        a0[1] = __shfl_sync(0xffffffffu, u1y, src);
        a1[0] = __shfl_sync(0xffffffffu, u1z, src);
        a1[1] = __shfl_sync(0xffffffffu, u1w, src);
        a0[2] = __shfl_sync(0xffffffffu, u2x, src);
        a0[3] = __shfl_sync(0xffffffffu, u2y, src);
        a1[2] = __shfl_sync(0xffffffffu, u2z, src);
        a1[3] = __shfl_sync(0xffffffffu, u2w, src);

        uint2 bl = s_bl[(s << 5) | lane];
        uint2 bh = s_bh[(s << 5) | lane];

        mma_tf32(d[0][0], a0, bl.x, bl.y);
        mma_tf32(d[0][1], a0, bh.x, bh.y);
        mma_tf32(d[1][0], a1, bl.x, bl.y);
        mma_tf32(d[1][1], a1, bh.x, bh.y);

        c1 = n1; c2 = n2;
    }

    float* vb = g_v + ((size_t)b * HW + pix0) * VD;
#pragma unroll
    for (int t = 0; t < 2; t++) {
#pragma unroll
        for (int h = 0; h < 2; h++) {
            *reinterpret_cast<float2*>(vb + (4 * gid + 2 * t) * VD + h * 8 + 2 * tg) =
                make_float2(d[t][h][0], d[t][h][1]);
            *reinterpret_cast<float2*>(vb + (4 * gid + 2 * t + 1) * VD + h * 8 + 2 * tg) =
                make_float2(d[t][h][2], d[t][h][3]);
        }
    }

    float s2[2][2];
#pragma unroll
    for (int h = 0; h < 2; h++) {
        s2[h][0] = d[0][h][0] + d[0][h][2] + d[1][h][0] + d[1][h][2];
        s2[h][1] = d[0][h][1] + d[0][h][3] + d[1][h][1] + d[1][h][3];
    }
#pragma unroll
    for (int off = 4; off < 32; off <<= 1) {
#pragma unroll
        for (int h = 0; h < 2; h++) {
            s2[h][0] += __shfl_xor_sync(0xffffffffu, s2[h][0], off);
            s2[h][1] += __shfl_xor_sync(0xffffffffu, s2[h][1], off);
        }
    }
    if (gid == 0) {
#pragma unroll
        for (int h = 0; h < 2; h++) {
            sred[warp][h * 8 + 2 * tg]     = s2[h][0];
            sred[warp][h * 8 + 2 * tg + 1] = s2[h][1];
        }
    }
    __syncthreads();
    if (tid < VD) {
        float t = 0.f;
#pragma unroll
        for (int w = 0; w < 8; w++) t += sred[w][tid];
        g_part[blockIdx.x * VD + tid] = t;
    }
}

// ======================================================================
// Pass 2: tree recursion, ONE block per batch (grid 32). Unchanged.
// ======================================================================
__global__ void __launch_bounds__(256) k_tree(const float* __restrict__ root_b,
                                              const float* __restrict__ level_w,
                                              const float* __restrict__ level_b,
                                              float* __restrict__ out) {
    const int b = blockIdx.x;
    const int tid = threadIdx.x;

    __shared__ float A[NCLS][VD][VD], Cv[NCLS][VD], Mu[NCLS][VD];
    __shared__ float An[NCLS][VD][VD], Cn[NCLS][VD], Mun[NCLS][VD];
    __shared__ float norms[NCLS];
    __shared__ int selsh;

    {
        int o = tid >> 4, i = tid & 15;
        A[0][o][i] = (o == i) ? 1.f : 0.f;
    }
    if (tid < VD) {
        float s = 0.f;
        for (int ch = 0; ch < 16; ch++) s += g_part[(b * 16 + ch) * VD + tid];
        Mu[0][tid] = s * (1.0f / (float)HW) + root_b[tid];
        Cv[0][tid] = 0.f;
    }
    __syncthreads();

    for (int level = 1; level < NCLS; level++) {
        const int prevN = level, newN = level + 1;
        const int off = ((level - 1) * (level + 2)) >> 1;   // 0,2,5,9

        if (tid < prevN) {
            float s = 0.f;
            for (int k = 0; k < VD; k++) s += Mu[tid][k] * Mu[tid][k];
            norms[tid] = sqrtf(s);
        }
        __syncthreads();

        if (tid < newN * VD) {
            const int node = tid >> 4, o = tid & 15;
            int pl = node - 1; if (pl < 0) pl = 0;
            int pr = node;     if (pr > prevN - 1) pr = prevN - 1;
            const int ps = (pl == pr) ? pl : ((norms[pr] > norms[pl]) ? pr : pl);

            const float* W = level_w + (off + node) * (VD * VD) + o * VD;
            const float bb = level_b[(off + node) * VD + o];
            float cm = bb, mm = bb;
            float arow[VD];
#pragma unroll
            for (int i = 0; i < VD; i++) arow[i] = 0.f;
            for (int k = 0; k < VD; k++) {
                const float w = W[k];
                cm += w * Cv[ps][k];
                mm += w * Mu[ps][k];
#pragma unroll
                for (int i = 0; i < VD; i++) arow[i] += w * A[ps][k][i];
            }
            Cn[node][o] = cm;
            Mun[node][o] = mm;
#pragma unroll
            for (int i = 0; i < VD; i++) An[node][o][i] = arow[i];
        }
        __syncthreads();

        for (int idx = tid; idx < newN * VD * VD; idx += 256) {
            int node = idx >> 8, r = idx & 255;
            A[node][r >> 4][r & 15] = An[node][r >> 4][r & 15];
        }
        if (tid < newN * VD) {
            Cv[tid >> 4][tid & 15] = Cn[tid >> 4][tid & 15];
            Mu[tid >> 4][tid & 15] = Mun[tid >> 4][tid & 15];
        }
        __syncthreads();
    }

    if (tid < NCLS) {
        float s = 0.f;
        for (int k = 0; k < VD; k++) s += Mu[tid][k] * Mu[tid][k];
        norms[tid] = sqrtf(s);
        out[b * NCLS + tid] = norms[tid];
    }
    __syncthreads();
    if (tid == 0) {
        int sel = 0; float best = norms[0];
        for (int n = 1; n < NCLS; n++) if (norms[n] > best) { best = norms[n]; sel = n; }
        selsh = sel;
        out[B * NCLS + B + b] = (float)sel;
    }
    __syncthreads();
    const int sel = selsh;
    g_Asel[b * 256 + tid] = A[sel][tid >> 4][tid & 15];
    if (tid < VD) {
        float s = Cv[sel][tid];
        for (int k = 0; k < VD; k++) s += A[sel][tid][k] * root_b[k];
        g_dvec[b * VD + tid] = s;
    }
}

// ======================================================================
// Pass 3 (tensor-core head + finisher): per warp, tiles of 32 px:
//   f = A_sel @ v^T + d (mma), per-px L2 norm (shfl), D->B permute (shfl),
//   MLP1 (mma, weights in registers) + bias + relu + w2-dot, accumulate.
// grid 128 = 4 blocks/batch, 8 warps/block, 4 tiles/warp.
// ======================================================================
__global__ void __launch_bounds__(256) k_head(const float* __restrict__ m1_w,
                                              const float* __restrict__ m1_b,
                                              const float* __restrict__ m2_w,
                                              const float* __restrict__ m2_b,
                                              float* __restrict__ out) {
    const int bq = blockIdx.x;              // 0..127
    const int b = bq >> 2, q = bq & 3;
    const int tid = threadIdx.x;
    const int warp = tid >> 5, lane = tid & 31;
    const int gid = lane >> 2, tg = lane & 3;

    // ---- stage 0: all weights as register fragments (L1/L2-cached LDGs) ----
    const float* As = g_Asel + b * 256;
    uint32_t aA[2][4];
#pragma unroll
    for (int kk = 0; kk < 2; kk++) {
        const int k0 = 8 * kk;
        aA[kk][0] = f2tf32(As[gid * VD + k0 + tg]);
        aA[kk][1] = f2tf32(As[(gid + 8) * VD + k0 + tg]);
        aA[kk][2] = f2tf32(As[gid * VD + k0 + tg + 4]);
        aA[kk][3] = f2tf32(As[(gid + 8) * VD + k0 + tg + 4]);
    }
    const float dv0 = g_dvec[b * VD + gid];
    const float dv8 = g_dvec[b * VD + gid + 8];

    uint32_t aW[4][2][4];
    float b1lo[4], b1hi[4], w2lo[4], w2hi[4];
#pragma unroll
    for (int mt = 0; mt < 4; mt++) {
        const int j0 = 16 * mt;
#pragma unroll
        for (int kk = 0; kk < 2; kk++) {
            const int k0 = 8 * kk;
            aW[mt][kk][0] = f2tf32(m1_w[(j0 + gid) * VD + k0 + tg]);
            aW[mt][kk][1] = f2tf32(m1_w[(j0 + gid + 8) * VD + k0 + tg]);
            aW[mt][kk][2] = f2tf32(m1_w[(j0 + gid) * VD + k0 + tg + 4]);
            aW[mt][kk][3] = f2tf32(m1_w[(j0 + gid + 8) * VD + k0 + tg + 4]);
        }
        b1lo[mt] = m1_b[j0 + gid];     b1hi[mt] = m1_b[j0 + gid + 8];
        w2lo[mt] = m2_w[j0 + gid];     w2hi[mt] = m2_w[j0 + gid + 8];
    }

    const int srcA = 4 * tg + (gid >> 1);        // b0 source lane
    const int srcB = 16 + 4 * tg + (gid >> 1);   // b1 source lane
    const bool odd = (gid & 1) != 0;

    float accsum = 0.f;

#pragma unroll 1
    for (int it = 0; it < 4; it++) {
        const int px0 = q * 1024 + it * 256 + warp * 32;
        const float* vb = g_v + ((size_t)b * HW + px0) * VD;

        // ---- f = A_sel @ v^T + d, then per-px normalize ----
        float Df[4][4];
#pragma unroll
        for (int nt = 0; nt < 4; nt++) {
            const float* vr = vb + (8 * nt + gid) * VD;
            uint32_t bv00 = f2tf32(vr[tg]),     bv01 = f2tf32(vr[tg + 4]);
            uint32_t bv10 = f2tf32(vr[tg + 8]), bv11 = f2tf32(vr[tg + 12]);

            Df[nt][0] = Df[nt][1] = Df[nt][2] = Df[nt][3] = 0.f;
            mma_tf32(Df[nt], aA[0], bv00, bv01);
            mma_tf32(Df[nt], aA[1], bv10, bv11);

            Df[nt][0] += dv0; Df[nt][1] += dv0;
            Df[nt][2] += dv8; Df[nt][3] += dv8;

            float p0 = Df[nt][0] * Df[nt][0] + Df[nt][2] * Df[nt][2];
            float p1 = Df[nt][1] * Df[nt][1] + Df[nt][3] * Df[nt][3];
#pragma unroll
            for (int off = 4; off < 32; off <<= 1) {
                p0 += __shfl_xor_sync(0xffffffffu, p0, off);
                p1 += __shfl_xor_sync(0xffffffffu, p1, off);
            }
            const float inv0 = 1.0f / (sqrtf(p0) + 1e-8f);
            const float inv1 = 1.0f / (sqrtf(p1) + 1e-8f);
            Df[nt][0] *= inv0; Df[nt][2] *= inv0;
            Df[nt][1] *= inv1; Df[nt][3] *= inv1;
        }

        // ---- permute D-layout f into B-fragments ----
        uint32_t Bf[4][2][2];
#pragma unroll
        for (int nt = 0; nt < 4; nt++) {
            float s0a = __shfl_sync(0xffffffffu, Df[nt][0], srcA);
            float s0b = __shfl_sync(0xffffffffu, Df[nt][1], srcA);
            float s1a = __shfl_sync(0xffffffffu, Df[nt][0], srcB);
            float s1b = __shfl_sync(0xffffffffu, Df[nt][1], srcB);
            Bf[nt][0][0] = f2tf32(odd ? s0b : s0a);
            Bf[nt][0][1] = f2tf32(odd ? s1b : s1a);
            float s2a = __shfl_sync(0xffffffffu, Df[nt][2], srcA);
            float s2b = __shfl_sync(0xffffffffu, Df[nt][3], srcA);
            float s3a = __shfl_sync(0xffffffffu, Df[nt][2], srcB);
            float s3b = __shfl_sync(0xffffffffu, Df[nt][3], srcB);
            Bf[nt][1][0] = f2tf32(odd ? s2b : s2a);
            Bf[nt][1][1] = f2tf32(odd ? s3b : s3a);
        }

        // ---- MLP: t = relu(m1_w @ f + b1); acc += w2 . t ----
#pragma unroll
        for (int mt = 0; mt < 4; mt++) {
#pragma unroll
            for (int nt = 0; nt < 4; nt++) {
                float Dt[4] = {0.f, 0.f, 0.f, 0.f};
                mma_tf32(Dt, aW[mt][0], Bf[nt][0][0], Bf[nt][0][1]);
                mma_tf32(Dt, aW[mt][1], Bf[nt][1][0], Bf[nt][1][1]);
                float t0 = fmaxf(Dt[0] + b1lo[mt], 0.f);
                float t1 = fmaxf(Dt[1] + b1lo[mt], 0.f);
                float t2 = fmaxf(Dt[2] + b1hi[mt], 0.f);
                float t3 = fmaxf(Dt[3] + b1hi[mt], 0.f);
                accsum += w2lo[mt] * (t0 + t1) + w2hi[mt] * (t2 + t3);
            }
        }
    }

    // ---- block reduce + finisher ----
    __shared__ float red[8];
    __shared__ int is_last;
#pragma unroll
    for (int off = 16; off; off >>= 1)
        accsum += __shfl_xor_sync(0xffffffffu, accsum, off);
    if (lane == 0) red[warp] = accsum;
    __syncthreads();
    if (tid == 0) {
        float t = 0.f;
#pragma unroll
        for (int w = 0; w < 8; w++) t += red[w];
        g_m2part[bq] = t;
        __threadfence();
        is_last = (atomicAdd(&g_ticket1, 1) == 127);
    }
    __syncthreads();

    if (is_last) {
        __threadfence();
        if (tid < B) {
            float s = 0.f;
#pragma unroll
            for (int c = 0; c < 4; c++) s += g_m2part[tid * 4 + c];
            const float x = s * (1.0f / (float)HW) + m2_b[0];
            out[B * NCLS + tid] = 0.75f / (1.0f + expf(-x)) + 0.75f;
        }
        if (tid == 0) g_ticket1 = 0;   // replay-safe reset
    }
}

// ======================================================================
extern "C" void kernel_launch(void* const* d_in, const int* in_sizes, int n_in,
                              void* d_out, int out_size) {
    const float* features = (const float*)d_in[0];
    const float* root_w   = (const float*)d_in[1];
    const float* root_b   = (const float*)d_in[2];
    const float* level_w  = (const float*)d_in[3];
    const float* level_b  = (const float*)d_in[4];
    const float* m1_w     = (const float*)d_in[5];
    const float* m1_b     = (const float*)d_in[6];
    const float* m2_w     = (const float*)d_in[7];
    const float* m2_b     = (const float*)d_in[8];
    float* out = (float*)d_out;

    k_root<<<B * 16, 256>>>(features, root_w);
    k_tree<<<B, 256>>>(root_b, level_w, level_b, out);
    k_head<<<B * 4, 256>>>(m1_w, m1_b, m2_w, m2_b, out);
}

// round 17
// speedup vs baseline: 4.2501x; 1.0004x over previous
#include <cuda_runtime.h>
#include <cuda_bf16.h>
#include <cstdint>

// Problem constants
#define B     32
#define IN_CH 512
#define VD    16
#define HW    4096          // 64*64
#define NCLS  5
#define KSTEPS 64           // IN_CH / 8

typedef unsigned long long ULL;

// ---------------- device scratch (no allocs allowed) ----------------
__device__ float g_v[(size_t)B * HW * VD];   // 8 MB: root conv output, (b, slot, 16)
__device__ float g_part[512 * VD];           // per-block partial sums of v
__device__ float g_Asel[B * VD * VD];        // selected leaf composition matrix
__device__ float g_dvec[B * VD];             // selected leaf offset
__device__ float g_m2part[256];              // per-block partial sums of m2
__device__ int   g_ticket1;                  // k_head finisher ticket

__device__ __forceinline__ uint32_t f2tf32(float x) {
    uint32_t r;
    asm("cvt.rna.tf32.f32 %0, %1;" : "=r"(r) : "f"(x));
    return r;
}
__device__ __forceinline__ void mma_tf32(float* d, const uint32_t* a, uint32_t b0, uint32_t b1) {
    asm volatile(
        "mma.sync.aligned.m16n8k8.row.col.f32.tf32.tf32.f32 "
        "{%0,%1,%2,%3}, {%4,%5,%6,%7}, {%8,%9}, {%0,%1,%2,%3};"
        : "+f"(d[0]), "+f"(d[1]), "+f"(d[2]), "+f"(d[3])
        : "r"(a[0]), "r"(a[1]), "r"(a[2]), "r"(a[3]), "r"(b0), "r"(b1));
}

// ======================================================================
// Pass 1 (tensor-core, full-line loads): v = root_w @ features per pixel.
// EXACT R15 mainloop (50.3us, 69% DRAM).
// ======================================================================
__global__ void __launch_bounds__(256, 4) k_root(const float* __restrict__ feat,
                                                 const float* __restrict__ root_w) {
    __shared__ uint2 s_bl[KSTEPS * 32];
    __shared__ uint2 s_bh[KSTEPS * 32];
    __shared__ float sred[8][VD];

    const int b     = blockIdx.x >> 4;
    const int chunk = blockIdx.x & 15;
    const int tid   = threadIdx.x;
    const int warp  = tid >> 5, lane = tid & 31;
    const int gid   = lane >> 2, tg = lane & 3;

    for (int idx = tid; idx < KSTEPS * 32; idx += 256) {
        int s = idx >> 5, l = idx & 31;
        int g = l >> 2, t = l & 3;
        int k = 8 * s + t;
        s_bl[idx] = make_uint2(f2tf32(root_w[g * IN_CH + k]),
                               f2tf32(root_w[g * IN_CH + k + 4]));
        s_bh[idx] = make_uint2(f2tf32(root_w[(g + 8) * IN_CH + k]),
                               f2tf32(root_w[(g + 8) * IN_CH + k + 4]));
    }
    __syncthreads();

    const int pix0 = chunk * 256 + warp * 32;
    const float* lp = feat + (size_t)b * (IN_CH * HW) + (size_t)(lane >> 3) * HW
                    + pix0 + 4 * (lane & 7);
    const int src = (tg << 3) | gid;

    float d[2][2][4];
#pragma unroll
    for (int t = 0; t < 2; t++)
#pragma unroll
        for (int h = 0; h < 2; h++)
#pragma unroll
            for (int j = 0; j < 4; j++) d[t][h][j] = 0.f;

    float4 c1 = *reinterpret_cast<const float4*>(lp);
    float4 c2 = *reinterpret_cast<const float4*>(lp + (size_t)4 * HW);

#pragma unroll 4
    for (int s = 0; s < KSTEPS; s++) {
        const float* np = lp + (size_t)(((s + 1) & (KSTEPS - 1)) * 8) * HW;
        float4 n1 = *reinterpret_cast<const float4*>(np);
        float4 n2 = *reinterpret_cast<const float4*>(np + (size_t)4 * HW);

        uint32_t u1x = f2tf32(c1.x), u1y = f2tf32(c1.y), u1z = f2tf32(c1.z), u1w = f2tf32(c1.w);
        uint32_t u2x = f2tf32(c2.x), u2y = f2tf32(c2.y), u2z = f2tf32(c2.z), u2w = f2tf32(c2.w);

        uint32_t a0[4], a1[4];
        a0[0] = __shfl_sync(0xffffffffu, u1x, src);
        a0[1] = __shfl_sync(0xffffffffu, u1y, src);
        a1[0] = __shfl_sync(0xffffffffu, u1z, src);
        a1[1] = __shfl_sync(0xffffffffu, u1w, src);
        a0[2] = __shfl_sync(0xffffffffu, u2x, src);
        a0[3] = __shfl_sync(0xffffffffu, u2y, src);
        a1[2] = __shfl_sync(0xffffffffu, u2z, src);
        a1[3] = __shfl_sync(0xffffffffu, u2w, src);

        uint2 bl = s_bl[(s << 5) | lane];
        uint2 bh = s_bh[(s << 5) | lane];

        mma_tf32(d[0][0], a0, bl.x, bl.y);
        mma_tf32(d[0][1], a0, bh.x, bh.y);
        mma_tf32(d[1][0], a1, bl.x, bl.y);
        mma_tf32(d[1][1], a1, bh.x, bh.y);

        c1 = n1; c2 = n2;
    }

    float* vb = g_v + ((size_t)b * HW + pix0) * VD;
#pragma unroll
    for (int t = 0; t < 2; t++) {
#pragma unroll
        for (int h = 0; h < 2; h++) {
            *reinterpret_cast<float2*>(vb + (4 * gid + 2 * t) * VD + h * 8 + 2 * tg) =
                make_float2(d[t][h][0], d[t][h][1]);
            *reinterpret_cast<float2*>(vb + (4 * gid + 2 * t + 1) * VD + h * 8 + 2 * tg) =
                make_float2(d[t][h][2], d[t][h][3]);
        }
    }

    float s2[2][2];
#pragma unroll
    for (int h = 0; h < 2; h++) {
        s2[h][0] = d[0][h][0] + d[0][h][2] + d[1][h][0] + d[1][h][2];
        s2[h][1] = d[0][h][1] + d[0][h][3] + d[1][h][1] + d[1][h][3];
    }
#pragma unroll
    for (int off = 4; off < 32; off <<= 1) {
#pragma unroll
        for (int h = 0; h < 2; h++) {
            s2[h][0] += __shfl_xor_sync(0xffffffffu, s2[h][0], off);
            s2[h][1] += __shfl_xor_sync(0xffffffffu, s2[h][1], off);
        }
    }
    if (gid == 0) {
#pragma unroll
        for (int h = 0; h < 2; h++) {
            sred[warp][h * 8 + 2 * tg]     = s2[h][0];
            sred[warp][h * 8 + 2 * tg + 1] = s2[h][1];
        }
    }
    __syncthreads();
    if (tid < VD) {
        float t = 0.f;
#pragma unroll
        for (int w = 0; w < 8; w++) t += sred[w][tid];
        g_part[blockIdx.x * VD + tid] = t;
    }
}

// ======================================================================
// Pass 2: tree recursion, ONE block per batch (grid 32). Unchanged.
// ======================================================================
__global__ void __launch_bounds__(256) k_tree(const float* __restrict__ root_b,
                                              const float* __restrict__ level_w,
                                              const float* __restrict__ level_b,
                                              float* __restrict__ out) {
    const int b = blockIdx.x;
    const int tid = threadIdx.x;

    __shared__ float A[NCLS][VD][VD], Cv[NCLS][VD], Mu[NCLS][VD];
    __shared__ float An[NCLS][VD][VD], Cn[NCLS][VD], Mun[NCLS][VD];
    __shared__ float norms[NCLS];
    __shared__ int selsh;

    {
        int o = tid >> 4, i = tid & 15;
        A[0][o][i] = (o == i) ? 1.f : 0.f;
    }
    if (tid < VD) {
        float s = 0.f;
        for (int ch = 0; ch < 16; ch++) s += g_part[(b * 16 + ch) * VD + tid];
        Mu[0][tid] = s * (1.0f / (float)HW) + root_b[tid];
        Cv[0][tid] = 0.f;
    }
    __syncthreads();

    for (int level = 1; level < NCLS; level++) {
        const int prevN = level, newN = level + 1;
        const int off = ((level - 1) * (level + 2)) >> 1;   // 0,2,5,9

        if (tid < prevN) {
            float s = 0.f;
            for (int k = 0; k < VD; k++) s += Mu[tid][k] * Mu[tid][k];
            norms[tid] = sqrtf(s);
        }
        __syncthreads();

        if (tid < newN * VD) {
            const int node = tid >> 4, o = tid & 15;
            int pl = node - 1; if (pl < 0) pl = 0;
            int pr = node;     if (pr > prevN - 1) pr = prevN - 1;
            const int ps = (pl == pr) ? pl : ((norms[pr] > norms[pl]) ? pr : pl);

            const float* W = level_w + (off + node) * (VD * VD) + o * VD;
            const float bb = level_b[(off + node) * VD + o];
            float cm = bb, mm = bb;
            float arow[VD];
#pragma unroll
            for (int i = 0; i < VD; i++) arow[i] = 0.f;
            for (int k = 0; k < VD; k++) {
                const float w = W[k];
                cm += w * Cv[ps][k];
                mm += w * Mu[ps][k];
#pragma unroll
                for (int i = 0; i < VD; i++) arow[i] += w * A[ps][k][i];
            }
            Cn[node][o] = cm;
            Mun[node][o] = mm;
#pragma unroll
            for (int i = 0; i < VD; i++) An[node][o][i] = arow[i];
        }
        __syncthreads();

        for (int idx = tid; idx < newN * VD * VD; idx += 256) {
            int node = idx >> 8, r = idx & 255;
            A[node][r >> 4][r & 15] = An[node][r >> 4][r & 15];
        }
        if (tid < newN * VD) {
            Cv[tid >> 4][tid & 15] = Cn[tid >> 4][tid & 15];
            Mu[tid >> 4][tid & 15] = Mun[tid >> 4][tid & 15];
        }
        __syncthreads();
    }

    if (tid < NCLS) {
        float s = 0.f;
        for (int k = 0; k < VD; k++) s += Mu[tid][k] * Mu[tid][k];
        norms[tid] = sqrtf(s);
        out[b * NCLS + tid] = norms[tid];
    }
    __syncthreads();
    if (tid == 0) {
        int sel = 0; float best = norms[0];
        for (int n = 1; n < NCLS; n++) if (norms[n] > best) { best = norms[n]; sel = n; }
        selsh = sel;
        out[B * NCLS + B + b] = (float)sel;
    }
    __syncthreads();
    const int sel = selsh;
    g_Asel[b * 256 + tid] = A[sel][tid >> 4][tid & 15];
    if (tid < VD) {
        float s = Cv[sel][tid];
        for (int k = 0; k < VD; k++) s += A[sel][tid][k] * root_b[k];
        g_dvec[b * VD + tid] = s;
    }
}

// ======================================================================
// Pass 3 (tensor-core head + finisher): per warp, tiles of 32 px:
//   f = A_sel @ v^T + d (mma), per-px L2 norm (shfl), D->B permute (shfl),
//   MLP1 (mma, weights in registers) + bias + relu + w2-dot, accumulate.
// grid 128 = 4 blocks/batch, 8 warps/block, 4 tiles/warp.
// ======================================================================
__global__ void __launch_bounds__(256) k_head(const float* __restrict__ m1_w,
                                              const float* __restrict__ m1_b,
                                              const float* __restrict__ m2_w,
                                              const float* __restrict__ m2_b,
                                              float* __restrict__ out) {
    const int bq = blockIdx.x;              // 0..127
    const int b = bq >> 2, q = bq & 3;
    const int tid = threadIdx.x;
    const int warp = tid >> 5, lane = tid & 31;
    const int gid = lane >> 2, tg = lane & 3;

    // ---- stage 0: all weights as register fragments (L1/L2-cached LDGs) ----
    const float* As = g_Asel + b * 256;
    uint32_t aA[2][4];
#pragma unroll
    for (int kk = 0; kk < 2; kk++) {
        const int k0 = 8 * kk;
        aA[kk][0] = f2tf32(As[gid * VD + k0 + tg]);
        aA[kk][1] = f2tf32(As[(gid + 8) * VD + k0 + tg]);
        aA[kk][2] = f2tf32(As[gid * VD + k0 + tg + 4]);
        aA[kk][3] = f2tf32(As[(gid + 8) * VD + k0 + tg + 4]);
    }
    const float dv0 = g_dvec[b * VD + gid];
    const float dv8 = g_dvec[b * VD + gid + 8];

    uint32_t aW[4][2][4];
    float b1lo[4], b1hi[4], w2lo[4], w2hi[4];
#pragma unroll
    for (int mt = 0; mt < 4; mt++) {
        const int j0 = 16 * mt;
#pragma unroll
        for (int kk = 0; kk < 2; kk++) {
            const int k0 = 8 * kk;
            aW[mt][kk][0] = f2tf32(m1_w[(j0 + gid) * VD + k0 + tg]);
            aW[mt][kk][1] = f2tf32(m1_w[(j0 + gid + 8) * VD + k0 + tg]);
            aW[mt][kk][2] = f2tf32(m1_w[(j0 + gid) * VD + k0 + tg + 4]);
            aW[mt][kk][3] = f2tf32(m1_w[(j0 + gid + 8) * VD + k0 + tg + 4]);
        }
        b1lo[mt] = m1_b[j0 + gid];     b1hi[mt] = m1_b[j0 + gid + 8];
        w2lo[mt] = m2_w[j0 + gid];     w2hi[mt] = m2_w[j0 + gid + 8];
    }

    const int srcA = 4 * tg + (gid >> 1);        // b0 source lane
    const int srcB = 16 + 4 * tg + (gid >> 1);   // b1 source lane
    const bool odd = (gid & 1) != 0;

    float accsum = 0.f;

#pragma unroll 1
    for (int it = 0; it < 4; it++) {
        const int px0 = q * 1024 + it * 256 + warp * 32;
        const float* vb = g_v + ((size_t)b * HW + px0) * VD;

        // ---- f = A_sel @ v^T + d, then per-px normalize ----
        float Df[4][4];
#pragma unroll
        for (int nt = 0; nt < 4; nt++) {
            const float* vr = vb + (8 * nt + gid) * VD;
            uint32_t bv00 = f2tf32(vr[tg]),     bv01 = f2tf32(vr[tg + 4]);
            uint32_t bv10 = f2tf32(vr[tg + 8]), bv11 = f2tf32(vr[tg + 12]);

            Df[nt][0] = Df[nt][1] = Df[nt][2] = Df[nt][3] = 0.f;
            mma_tf32(Df[nt], aA[0], bv00, bv01);
            mma_tf32(Df[nt], aA[1], bv10, bv11);

            Df[nt][0] += dv0; Df[nt][1] += dv0;
            Df[nt][2] += dv8; Df[nt][3] += dv8;

            float p0 = Df[nt][0] * Df[nt][0] + Df[nt][2] * Df[nt][2];
            float p1 = Df[nt][1] * Df[nt][1] + Df[nt][3] * Df[nt][3];
#pragma unroll
            for (int off = 4; off < 32; off <<= 1) {
                p0 += __shfl_xor_sync(0xffffffffu, p0, off);
                p1 += __shfl_xor_sync(0xffffffffu, p1, off);
            }
            const float inv0 = 1.0f / (sqrtf(p0) + 1e-8f);
            const float inv1 = 1.0f / (sqrtf(p1) + 1e-8f);
            Df[nt][0] *= inv0; Df[nt][2] *= inv0;
            Df[nt][1] *= inv1; Df[nt][3] *= inv1;
        }

        // ---- permute D-layout f into B-fragments ----
        uint32_t Bf[4][2][2];
#pragma unroll
        for (int nt = 0; nt < 4; nt++) {
            float s0a = __shfl_sync(0xffffffffu, Df[nt][0], srcA);
            float s0b = __shfl_sync(0xffffffffu, Df[nt][1], srcA);
            float s1a = __shfl_sync(0xffffffffu, Df[nt][0], srcB);
            float s1b = __shfl_sync(0xffffffffu, Df[nt][1], srcB);
            Bf[nt][0][0] = f2tf32(odd ? s0b : s0a);
            Bf[nt][0][1] = f2tf32(odd ? s1b : s1a);
            float s2a = __shfl_sync(0xffffffffu, Df[nt][2], srcA);
            float s2b = __shfl_sync(0xffffffffu, Df[nt][3], srcA);
            float s3a = __shfl_sync(0xffffffffu, Df[nt][2], srcB);
            float s3b = __shfl_sync(0xffffffffu, Df[nt][3], srcB);
            Bf[nt][1][0] = f2tf32(odd ? s2b : s2a);
            Bf[nt][1][1] = f2tf32(odd ? s3b : s3a);
        }

        // ---- MLP: t = relu(m1_w @ f + b1); acc += w2 . t ----
#pragma unroll
        for (int mt = 0; mt < 4; mt++) {
#pragma unroll
            for (int nt = 0; nt < 4; nt++) {
                float Dt[4] = {0.f, 0.f, 0.f, 0.f};
                mma_tf32(Dt, aW[mt][0], Bf[nt][0][0], Bf[nt][0][1]);
                mma_tf32(Dt, aW[mt][1], Bf[nt][1][0], Bf[nt][1][1]);
                float t0 = fmaxf(Dt[0] + b1lo[mt], 0.f);
                float t1 = fmaxf(Dt[1] + b1lo[mt], 0.f);
                float t2 = fmaxf(Dt[2] + b1hi[mt], 0.f);
                float t3 = fmaxf(Dt[3] + b1hi[mt], 0.f);
                accsum += w2lo[mt] * (t0 + t1) + w2hi[mt] * (t2 + t3);
            }
        }
    }

    // ---- block reduce + finisher ----
    __shared__ float red[8];
    __shared__ int is_last;
#pragma unroll
    for (int off = 16; off; off >>= 1)
        accsum += __shfl_xor_sync(0xffffffffu, accsum, off);
    if (lane == 0) red[warp] = accsum;
    __syncthreads();
    if (tid == 0) {
        float t = 0.f;
#pragma unroll
        for (int w = 0; w < 8; w++) t += red[w];
        g_m2part[bq] = t;
        __threadfence();
        is_last = (atomicAdd(&g_ticket1, 1) == 127);
    }
    __syncthreads();

    if (is_last) {
        __threadfence();
        if (tid < B) {
            float s = 0.f;
#pragma unroll
            for (int c = 0; c < 4; c++) s += g_m2part[tid * 4 + c];
            const float x = s * (1.0f / (float)HW) + m2_b[0];
            out[B * NCLS + tid] = 0.75f / (1.0f + expf(-x)) + 0.75f;
        }
        if (tid == 0) g_ticket1 = 0;   // replay-safe reset
    }
}

// ======================================================================
extern "C" void kernel_launch(void* const* d_in, const int* in_sizes, int n_in,
                              void* d_out, int out_size) {
    const float* features = (const float*)d_in[0];
    const float* root_w   = (const float*)d_in[1];
    const float* root_b   = (const float*)d_in[2];
    const float* level_w  = (const float*)d_in[3];
    const float* level_b  = (const float*)d_in[4];
    const float* m1_w     = (const float*)d_in[5];
    const float* m1_b     = (const float*)d_in[6];
    const float* m2_w     = (const float*)d_in[7];
    const float* m2_b     = (const float*)d_in[8];
    float* out = (float*)d_out;

    k_root<<<B * 16, 256>>>(features, root_w);
    k_tree<<<B, 256>>>(root_b, level_w, level_b, out);
    k_head<<<B * 4, 256>>>(m1_w, m1_b, m2_w, m2_b, out);
}